// round 10
// baseline (speedup 1.0000x reference)
#include <cuda_runtime.h>
#include <cuda_bf16.h>
#include <mma.h>
using namespace nvcuda;

#define BB 16
#define TT 128
#define HH 512
#define VV 32000
#define GG 1536          // 3*H
#define MROWS (BB*TT)    // 2048
#define NBLK 128         // persistent GRU grid

// ---------------- scratch (device globals; no runtime allocation) ----------
__device__ float g_xp[TT * BB * GG];             // [t*B+b][3H] incl. b_ih  (12.6 MB)
__device__ float g_hbuf[2][BB * HH];             // double-buffered GRU state
__device__ __nv_bfloat16 g_hs[MROWS * HH];       // gru_out bf16, row = b*T+t (2 MB)
__device__ __nv_bfloat16 g_wout[VV * HH];        // bf16 w_out (32.8 MB)
__device__ volatile unsigned g_arrive[NBLK];     // monotone per-CTA flags

// ---------------- fast exp on FMA pipe (valid for x <= 0) ------------------
__device__ __forceinline__ float fexp_neg(float x) {
    float y = fmaxf(x * 1.442695041f, -100.0f);       // log2(e)*x, clamped
    float t = y + 12582912.0f;                        // round-to-nearest int
    int   n = __float_as_int(t) - 0x4B400000;         // integer part
    float f = y - (t - 12582912.0f);                  // frac in [-0.5, 0.5]
    float p = 1.33335581e-3f;
    p = fmaf(p, f, 9.61812910e-3f);
    p = fmaf(p, f, 5.55041087e-2f);
    p = fmaf(p, f, 2.40226507e-1f);
    p = fmaf(p, f, 6.93147181e-1f);
    p = fmaf(p, f, 1.0f);                             // 2^f
    return __int_as_float(__float_as_int(p) + (n << 23));
}

// ---------------- K0: w_out -> bf16 ---------------------------------------
__global__ void __launch_bounds__(256) k_convert(const float* __restrict__ w) {
    const int n4 = VV * HH / 4;
    for (int i = blockIdx.x * blockDim.x + threadIdx.x; i < n4;
         i += gridDim.x * blockDim.x) {
        float4 v = ((const float4*)w)[i];
        ((__nv_bfloat162*)g_wout)[2 * i + 0] = __floats2bfloat162_rn(v.x, v.y);
        ((__nv_bfloat162*)g_wout)[2 * i + 1] = __floats2bfloat162_rn(v.z, v.w);
    }
}

// ---------------- K1: x_proj = relu(emb[tok]) @ w_ih^T + b_ih --------------
__global__ void __launch_bounds__(256) k_xproj(const float* __restrict__ emb,
                                               const int* __restrict__ tgt,
                                               const float* __restrict__ w_ih,
                                               const float* __restrict__ b_ih) {
    __shared__ float As[8][128];
    __shared__ float Bs[8][128];
    __shared__ int toks[128];
    const int tid = threadIdx.x;
    const int m0 = blockIdx.y * 128, n0 = blockIdx.x * 128;

    if (tid < 128) {
        int m = m0 + tid;
        int t = m >> 4, b = m & 15;
        toks[tid] = (t == 0) ? 1 : tgt[b * TT + t - 1];  // BOS = 1
    }
    __syncthreads();

    const int ra = tid >> 1, kc = (tid & 1) * 4;
    const float* arow = emb + (size_t)toks[ra] * HH;
    const float* brow = w_ih + (size_t)(n0 + ra) * HH;
    const int tx = tid & 15, ty = tid >> 4;

    float acc[8][8] = {};
    for (int k0 = 0; k0 < HH; k0 += 8) {
        float4 av = *(const float4*)(arow + k0 + kc);
        float4 bv = *(const float4*)(brow + k0 + kc);
        av.x = fmaxf(av.x, 0.f); av.y = fmaxf(av.y, 0.f);
        av.z = fmaxf(av.z, 0.f); av.w = fmaxf(av.w, 0.f);
        __syncthreads();
        As[kc + 0][ra] = av.x; As[kc + 1][ra] = av.y;
        As[kc + 2][ra] = av.z; As[kc + 3][ra] = av.w;
        Bs[kc + 0][ra] = bv.x; Bs[kc + 1][ra] = bv.y;
        Bs[kc + 2][ra] = bv.z; Bs[kc + 3][ra] = bv.w;
        __syncthreads();
#pragma unroll
        for (int k = 0; k < 8; k++) {
            float4 a0 = *(float4*)&As[k][ty * 8];
            float4 a1 = *(float4*)&As[k][ty * 8 + 4];
            float4 b0 = *(float4*)&Bs[k][tx * 8];
            float4 b1 = *(float4*)&Bs[k][tx * 8 + 4];
            float xv[8] = {a0.x, a0.y, a0.z, a0.w, a1.x, a1.y, a1.z, a1.w};
            float yv[8] = {b0.x, b0.y, b0.z, b0.w, b1.x, b1.y, b1.z, b1.w};
#pragma unroll
            for (int i = 0; i < 8; i++)
#pragma unroll
                for (int j = 0; j < 8; j++) acc[i][j] += xv[i] * yv[j];
        }
    }
    const float4 bi0 = *(const float4*)&b_ih[n0 + tx * 8];
    const float4 bi1 = *(const float4*)&b_ih[n0 + tx * 8 + 4];
#pragma unroll
    for (int i = 0; i < 8; i++) {
        float* orow = g_xp + (size_t)(m0 + ty * 8 + i) * GG + n0 + tx * 8;
        float4 o0, o1;
        o0.x = acc[i][0] + bi0.x; o0.y = acc[i][1] + bi0.y;
        o0.z = acc[i][2] + bi0.z; o0.w = acc[i][3] + bi0.w;
        o1.x = acc[i][4] + bi1.x; o1.y = acc[i][5] + bi1.y;
        o1.z = acc[i][6] + bi1.z; o1.w = acc[i][7] + bi1.w;
        *(float4*)orow = o0;
        *(float4*)(orow + 4) = o1;
    }
}

// ---------------- K2: persistent GRU scan ----------------------------------
// 128 blocks x 256 threads. Warp pair owns one j; warp handles 8 batches.
// ALL-TO-ALL barrier: each CTA publishes a monotone flag (release pattern:
// bar.sync -> tid0 cumulative fence -> flag store); every CTA's tids 0..127
// poll all 128 flags directly. One L2 round trip on the critical path.
__global__ void __launch_bounds__(256) k_gru(const float* __restrict__ eh,
                                             const float* __restrict__ w_hh,
                                             const float* __restrict__ b_hh,
                                             float* __restrict__ out) {
    __shared__ float hsm[BB * HH];  // 32 KB
    const int tid = threadIdx.x;
    const int lane = tid & 31, warp = tid >> 5;
    const int j = (blockIdx.x << 2) + (warp >> 1);
    const int bbase = (warp & 1) * 8;
    const unsigned base = g_arrive[blockIdx.x];  // all flags equal at entry

    float wr[16], wz[16], wn[16];
    {
        const float* p0 = w_hh + (size_t)j * HH;
        const float* p1 = w_hh + (size_t)(j + 512) * HH;
        const float* p2 = w_hh + (size_t)(j + 1024) * HH;
#pragma unroll
        for (int m = 0; m < 16; m++) {
            wr[m] = p0[lane + 32 * m];
            wz[m] = p1[lane + 32 * m];
            wn[m] = p2[lane + 32 * m];
        }
    }
    const float bhr = b_hh[j], bhz = b_hh[j + 512], bhn = b_hh[j + 1024];

    for (int i = tid; i < BB * HH; i += 256) hsm[i] = eh[i];
    __syncthreads();

    for (int t = 0; t < TT; t++) {
        const float* xpt = g_xp + (size_t)t * BB * GG;

        // prefetch this step's per-(b,j) inputs early (lanes 0..7 use them)
        float xr = 0.f, xz = 0.f, xn = 0.f, hold = 0.f;
        if (lane < 8) {
            const float* xpb = xpt + (size_t)(bbase + lane) * GG;
            xr = __ldcg(&xpb[j]);
            xz = __ldcg(&xpb[j + 512]);
            xn = __ldcg(&xpb[j + 1024]);
            hold = hsm[(bbase + lane) * HH + j];
        }

        float rr = 0.f, zz = 0.f, nnacc = 0.f;
#pragma unroll
        for (int q = 0; q < 8; q++) {
            const float* hb = hsm + (bbase + q) * HH;
            float ar = 0.f, az = 0.f, an = 0.f;
#pragma unroll
            for (int m = 0; m < 16; m++) {
                float hv = hb[lane + 32 * m];
                ar += hv * wr[m]; az += hv * wz[m]; an += hv * wn[m];
            }
#pragma unroll
            for (int off = 16; off; off >>= 1) {
                ar += __shfl_xor_sync(0xFFFFFFFFu, ar, off);
                az += __shfl_xor_sync(0xFFFFFFFFu, az, off);
                an += __shfl_xor_sync(0xFFFFFFFFu, an, off);
            }
            if (lane == q) { rr = ar; zz = az; nnacc = an; }
        }
        const int nb = (t + 1) & 1;
        if (lane < 8) {
            const int b = bbase + lane;
            float r = __fdividef(1.f, 1.f + __expf(-(xr + rr + bhr)));
            float z = __fdividef(1.f, 1.f + __expf(-(xz + zz + bhz)));
            float targ = xn + r * (nnacc + bhn);
            targ = fminf(fmaxf(targ, -15.f), 15.f);
            float e2 = __expf(2.f * targ);
            float nv = __fdividef(e2 - 1.f, e2 + 1.f);     // tanh
            float hnew = (1.f - z) * nv + z * hold;
            g_hbuf[nb][b * HH + j] = hnew;
            g_hs[((size_t)b * TT + t) * HH + j] = __float2bfloat16(hnew);
        }

        // ---- all-to-all grid barrier (monotone flags) ----
        __syncthreads();
        const unsigned tgt = base + (unsigned)t + 1u;
        if (tid == 0) {
            __threadfence();                   // cumulative: publish CTA's stores
            g_arrive[blockIdx.x] = tgt;
        }
        if (tid < NBLK) { while (g_arrive[tid] < tgt) { } }
        __syncthreads();

        // reload full h (float4)
        {
            const float4* src = (const float4*)g_hbuf[nb];
            float4* dst = (float4*)hsm;
#pragma unroll
            for (int i = 0; i < 8; i++) dst[tid + 256 * i] = __ldcg(&src[tid + 256 * i]);
        }
        __syncthreads();
    }
    // hidden output (fp32) appended after log_probs; final buffer is nb=0
    if (blockIdx.x == 0) {
        for (int i = tid; i < BB * HH; i += 256)
            out[(size_t)MROWS * VV + i] = __ldcg(&g_hbuf[0][i]);
    }
}

// ---------------- K3: logits = gru_out @ w_out^T (bf16 WMMA, f32 acc) ------
// 128x256 block tile, 8 warps (2x4), 64x64 warp tile, LD=40 (conflict-free),
// 4-stage cp.async pipeline (120 KB dynamic smem).
#define LG_LD 40
#define A_ST (128 * LG_LD)   // 5120 elems per A stage
#define B_ST (256 * LG_LD)   // 10240 elems per B stage
#define NSTG 4

__device__ __forceinline__ void cp16(__nv_bfloat16* smem_dst, const __nv_bfloat16* gsrc) {
    unsigned sa = (unsigned)__cvta_generic_to_shared(smem_dst);
    asm volatile("cp.async.cg.shared.global [%0], [%1], 16;" :: "r"(sa), "l"(gsrc));
}

__global__ void __launch_bounds__(256) k_logits(float* __restrict__ out) {
    extern __shared__ __nv_bfloat16 smbuf[];
    const int tid = threadIdx.x, warp = tid >> 5;
    const int wm = warp & 1, wn = warp >> 1;     // 2 x 4
    const int m0 = blockIdx.y * 128;
    const int n0 = blockIdx.x * 256;

    wmma::fragment<wmma::accumulator, 16, 16, 16, float> acc[4][4];
#pragma unroll
    for (int i = 0; i < 4; i++)
#pragma unroll
        for (int jj = 0; jj < 4; jj++) wmma::fill_fragment(acc[i][jj], 0.f);

    auto load_stage = [&](int s, int kb) {
        const int k0 = kb * 32;
        __nv_bfloat16* As = smbuf + s * A_ST;
        __nv_bfloat16* Bs = smbuf + NSTG * A_ST + s * B_ST;
#pragma unroll
        for (int idx = tid; idx < 512; idx += 256) {      // A: 128x32
            const int r = idx >> 2, c = (idx & 3) * 8;
            cp16(&As[r * LG_LD + c], &g_hs[(size_t)(m0 + r) * HH + k0 + c]);
        }
#pragma unroll
        for (int idx = tid; idx < 1024; idx += 256) {     // B: 256x32
            const int r = idx >> 2, c = (idx & 3) * 8;
            cp16(&Bs[r * LG_LD + c], &g_wout[(size_t)(n0 + r) * HH + k0 + c]);
        }
    };

    // prologue: stages 0..2 in flight
#pragma unroll
    for (int s = 0; s < 3; s++) {
        load_stage(s, s);
        asm volatile("cp.async.commit_group;");
    }

    for (int kb = 0; kb < 16; kb++) {
        asm volatile("cp.async.wait_group 2;");   // stage kb complete
        __syncthreads();                          // all warps done with kb-1's buf
        if (kb + 3 < 16) load_stage((kb + 3) & (NSTG - 1), kb + 3);
        asm volatile("cp.async.commit_group;");   // (may be empty near tail)

        const __nv_bfloat16* As = smbuf + (kb & (NSTG - 1)) * A_ST;
        const __nv_bfloat16* Bs = smbuf + NSTG * A_ST + (kb & (NSTG - 1)) * B_ST;
#pragma unroll
        for (int kk = 0; kk < 32; kk += 16) {
            wmma::fragment<wmma::matrix_a, 16, 16, 16, __nv_bfloat16,
                           wmma::row_major> af[4];
            wmma::fragment<wmma::matrix_b, 16, 16, 16, __nv_bfloat16,
                           wmma::col_major> bf[4];
#pragma unroll
            for (int i = 0; i < 4; i++)
                wmma::load_matrix_sync(af[i], &As[(wm * 64 + i * 16) * LG_LD + kk], LG_LD);
#pragma unroll
            for (int jj = 0; jj < 4; jj++)
                wmma::load_matrix_sync(bf[jj], &Bs[(wn * 64 + jj * 16) * LG_LD + kk], LG_LD);
#pragma unroll
            for (int i = 0; i < 4; i++)
#pragma unroll
                for (int jj = 0; jj < 4; jj++)
                    wmma::mma_sync(acc[i][jj], af[i], bf[jj], acc[i][jj]);
        }
    }
    __syncthreads();
#pragma unroll
    for (int i = 0; i < 4; i++)
#pragma unroll
        for (int jj = 0; jj < 4; jj++)
            wmma::store_matrix_sync(
                &out[(size_t)(m0 + wm * 64 + i * 16) * VV + n0 + wn * 64 + jj * 16],
                acc[i][jj], VV, wmma::mem_row_major);
}

// ---------------- K4: in-place log_softmax (FMA-pipe exp, bias folded) -----
__global__ void __launch_bounds__(256) k_lsm(const float* __restrict__ b_out,
                                             float* __restrict__ out) {
    __shared__ float sm[256], ss[256];
    const int tid = threadIdx.x;
    const size_t row = blockIdx.x;
    float* lg = out + row * VV;

    float m = -1e30f, s = 0.f;
    for (int i = tid; i < VV; i += 256) {
        float x = lg[i] + __ldg(&b_out[i]);
        if (x > m) { s = fmaf(s, fexp_neg(m - x), 1.f); m = x; }
        else s += fexp_neg(x - m);
    }
    sm[tid] = m; ss[tid] = s;
    __syncthreads();
    for (int off = 128; off; off >>= 1) {
        if (tid < off) {
            float m2 = sm[tid + off], s2 = ss[tid + off];
            float M = fmaxf(sm[tid], m2);
            ss[tid] = ss[tid] * fexp_neg(sm[tid] - M) + s2 * fexp_neg(m2 - M);
            sm[tid] = M;
        }
        __syncthreads();
    }
    const float lse = sm[0] + logf(ss[0]);
    for (int i = tid; i < VV; i += 256) lg[i] = lg[i] + __ldg(&b_out[i]) - lse;
}

// ---------------- launch ---------------------------------------------------
extern "C" void kernel_launch(void* const* d_in, const int* in_sizes, int n_in,
                              void* d_out, int out_size) {
    const float* enc_hidden = (const float*)d_in[1];
    const int*   tgt        = (const int*)d_in[2];
    const float* emb        = (const float*)d_in[3];
    const float* b_ih       = (const float*)d_in[5];
    const float* w_ih       = (const float*)d_in[4];
    const float* w_hh       = (const float*)d_in[6];
    const float* b_hh       = (const float*)d_in[7];
    const float* w_out      = (const float*)d_in[8];
    const float* b_out      = (const float*)d_in[9];
    float* out = (float*)d_out;

    const int lg_smem = NSTG * (A_ST + B_ST) * (int)sizeof(__nv_bfloat16);
    cudaFuncSetAttribute(k_logits, cudaFuncAttributeMaxDynamicSharedMemorySize,
                         lg_smem);

    k_convert<<<1024, 256>>>(w_out);

    dim3 gx(GG / 128, MROWS / 128);     // (12, 16)
    k_xproj<<<gx, 256>>>(emb, tgt, w_ih, b_ih);

    k_gru<<<NBLK, 256>>>(enc_hidden, w_hh, b_hh, out);

    dim3 gl(VV / 256, MROWS / 128);     // (125, 16)
    k_logits<<<gl, 256, lg_smem>>>(out);

    k_lsm<<<MROWS, 256>>>(b_out, out);
}

// round 12
// speedup vs baseline: 1.4542x; 1.4542x over previous
#include <cuda_runtime.h>
#include <cuda_bf16.h>
#include <mma.h>
using namespace nvcuda;

#define BB 16
#define TT 128
#define HH 512
#define VV 32000
#define GG 1536          // 3*H
#define MROWS (BB*TT)    // 2048
#define NBLK 128         // persistent GRU grid

// ---------------- scratch (device globals; no runtime allocation) ----------
__device__ float g_xp[TT * BB * GG];             // [t*B+b][3H] incl. b_ih  (12.6 MB)
__device__ float g_hbuf[2][BB * HH];             // double-buffered GRU state
__device__ __nv_bfloat16 g_hs[MROWS * HH];       // gru_out bf16, row = b*T+t (2 MB)
__device__ __nv_bfloat16 g_wout[VV * HH];        // bf16 w_out (32.8 MB)
__device__ volatile unsigned g_arrive[NBLK];     // monotone arrival flags
__device__ volatile unsigned g_gen2;             // monotone release word

// ---------------- fast exp on FMA pipe (valid for x <= 0) ------------------
__device__ __forceinline__ float fexp_neg(float x) {
    float y = fmaxf(x * 1.442695041f, -100.0f);       // log2(e)*x, clamped
    float t = y + 12582912.0f;                        // round-to-nearest int
    int   n = __float_as_int(t) - 0x4B400000;         // integer part
    float f = y - (t - 12582912.0f);                  // frac in [-0.5, 0.5]
    float p = 1.33335581e-3f;
    p = fmaf(p, f, 9.61812910e-3f);
    p = fmaf(p, f, 5.55041087e-2f);
    p = fmaf(p, f, 2.40226507e-1f);
    p = fmaf(p, f, 6.93147181e-1f);
    p = fmaf(p, f, 1.0f);                             // 2^f
    return __int_as_float(__float_as_int(p) + (n << 23));
}

// ---------------- K0: w_out -> bf16 ---------------------------------------
__global__ void __launch_bounds__(256) k_convert(const float* __restrict__ w) {
    const int n4 = VV * HH / 4;
    for (int i = blockIdx.x * blockDim.x + threadIdx.x; i < n4;
         i += gridDim.x * blockDim.x) {
        float4 v = ((const float4*)w)[i];
        ((__nv_bfloat162*)g_wout)[2 * i + 0] = __floats2bfloat162_rn(v.x, v.y);
        ((__nv_bfloat162*)g_wout)[2 * i + 1] = __floats2bfloat162_rn(v.z, v.w);
    }
}

// ---------------- K1: x_proj = relu(emb[tok]) @ w_ih^T + b_ih --------------
__global__ void __launch_bounds__(256) k_xproj(const float* __restrict__ emb,
                                               const int* __restrict__ tgt,
                                               const float* __restrict__ w_ih,
                                               const float* __restrict__ b_ih) {
    __shared__ float As[8][128];
    __shared__ float Bs[8][128];
    __shared__ int toks[128];
    const int tid = threadIdx.x;
    const int m0 = blockIdx.y * 128, n0 = blockIdx.x * 128;

    if (tid < 128) {
        int m = m0 + tid;
        int t = m >> 4, b = m & 15;
        toks[tid] = (t == 0) ? 1 : tgt[b * TT + t - 1];  // BOS = 1
    }
    __syncthreads();

    const int ra = tid >> 1, kc = (tid & 1) * 4;
    const float* arow = emb + (size_t)toks[ra] * HH;
    const float* brow = w_ih + (size_t)(n0 + ra) * HH;
    const int tx = tid & 15, ty = tid >> 4;

    float acc[8][8] = {};
    for (int k0 = 0; k0 < HH; k0 += 8) {
        float4 av = *(const float4*)(arow + k0 + kc);
        float4 bv = *(const float4*)(brow + k0 + kc);
        av.x = fmaxf(av.x, 0.f); av.y = fmaxf(av.y, 0.f);
        av.z = fmaxf(av.z, 0.f); av.w = fmaxf(av.w, 0.f);
        __syncthreads();
        As[kc + 0][ra] = av.x; As[kc + 1][ra] = av.y;
        As[kc + 2][ra] = av.z; As[kc + 3][ra] = av.w;
        Bs[kc + 0][ra] = bv.x; Bs[kc + 1][ra] = bv.y;
        Bs[kc + 2][ra] = bv.z; Bs[kc + 3][ra] = bv.w;
        __syncthreads();
#pragma unroll
        for (int k = 0; k < 8; k++) {
            float4 a0 = *(float4*)&As[k][ty * 8];
            float4 a1 = *(float4*)&As[k][ty * 8 + 4];
            float4 b0 = *(float4*)&Bs[k][tx * 8];
            float4 b1 = *(float4*)&Bs[k][tx * 8 + 4];
            float xv[8] = {a0.x, a0.y, a0.z, a0.w, a1.x, a1.y, a1.z, a1.w};
            float yv[8] = {b0.x, b0.y, b0.z, b0.w, b1.x, b1.y, b1.z, b1.w};
#pragma unroll
            for (int i = 0; i < 8; i++)
#pragma unroll
                for (int j = 0; j < 8; j++) acc[i][j] += xv[i] * yv[j];
        }
    }
    const float4 bi0 = *(const float4*)&b_ih[n0 + tx * 8];
    const float4 bi1 = *(const float4*)&b_ih[n0 + tx * 8 + 4];
#pragma unroll
    for (int i = 0; i < 8; i++) {
        float* orow = g_xp + (size_t)(m0 + ty * 8 + i) * GG + n0 + tx * 8;
        float4 o0, o1;
        o0.x = acc[i][0] + bi0.x; o0.y = acc[i][1] + bi0.y;
        o0.z = acc[i][2] + bi0.z; o0.w = acc[i][3] + bi0.w;
        o1.x = acc[i][4] + bi1.x; o1.y = acc[i][5] + bi1.y;
        o1.z = acc[i][6] + bi1.z; o1.w = acc[i][7] + bi1.w;
        *(float4*)orow = o0;
        *(float4*)(orow + 4) = o1;
    }
}

// ---------------- K2: persistent GRU scan ----------------------------------
// 128 blocks x 512 threads (16 warps, 4/SMSP). Warp w owns j = bid*4+(w>>2)
// and batches (w&3)*4..+3. Lane l holds w[j][128c + 4l + k] so h is read via
// 4 conflict-free LDS.128 per dot. Reduction: interleaved 3-way shfl
// butterfly (chains overlap; 4 warps/SMSP hide the latency).
// Barrier: R7-proven aggregator (monotone flags + release word).
__global__ void __launch_bounds__(512) k_gru(const float* __restrict__ eh,
                                             const float* __restrict__ w_hh,
                                             const float* __restrict__ b_hh,
                                             float* __restrict__ out) {
    __shared__ float hsm[BB * HH];  // 32 KB
    const int tid = threadIdx.x;
    const int lane = tid & 31, warp = tid >> 5;
    const int j = (blockIdx.x << 2) + (warp >> 2);
    const int bbase = (warp & 3) * 4;
    const unsigned base = g_gen2;   // value left by previous run (0 first run)

    float4 wr4[4], wz4[4], wn4[4];
    {
        const float* p0 = w_hh + (size_t)j * HH;
        const float* p1 = w_hh + (size_t)(j + 512) * HH;
        const float* p2 = w_hh + (size_t)(j + 1024) * HH;
#pragma unroll
        for (int c = 0; c < 4; c++) {
            wr4[c] = *(const float4*)&p0[128 * c + lane * 4];
            wz4[c] = *(const float4*)&p1[128 * c + lane * 4];
            wn4[c] = *(const float4*)&p2[128 * c + lane * 4];
        }
    }
    const float bhr = b_hh[j], bhz = b_hh[j + 512], bhn = b_hh[j + 1024];

    {
        const float4* src = (const float4*)eh;
        float4* dst = (float4*)hsm;
#pragma unroll
        for (int i = 0; i < 4; i++) dst[tid + 512 * i] = src[tid + 512 * i];
    }
    __syncthreads();

    for (int t = 0; t < TT; t++) {
        const float* xpt = g_xp + (size_t)t * BB * GG;

        // prefetch per-(b,j) inputs (lanes 0..3 own batches bbase..bbase+3)
        float xr = 0.f, xz = 0.f, xn = 0.f, hold = 0.f;
        if (lane < 4) {
            const float* xpb = xpt + (size_t)(bbase + lane) * GG;
            xr = __ldcg(&xpb[j]);
            xz = __ldcg(&xpb[j + 512]);
            xn = __ldcg(&xpb[j + 1024]);
            hold = hsm[(bbase + lane) * HH + j];
        }

        float rr = 0.f, zz = 0.f, nnacc = 0.f;
#pragma unroll
        for (int q = 0; q < 4; q++) {
            const float* hb = hsm + (bbase + q) * HH;
            float ar = 0.f, az = 0.f, an = 0.f;
#pragma unroll
            for (int c = 0; c < 4; c++) {
                float4 hv = *(const float4*)&hb[128 * c + lane * 4];
                ar += hv.x * wr4[c].x + hv.y * wr4[c].y + hv.z * wr4[c].z + hv.w * wr4[c].w;
                az += hv.x * wz4[c].x + hv.y * wz4[c].y + hv.z * wz4[c].z + hv.w * wz4[c].w;
                an += hv.x * wn4[c].x + hv.y * wn4[c].y + hv.z * wn4[c].z + hv.w * wn4[c].w;
            }
#pragma unroll
            for (int off = 16; off; off >>= 1) {    // 3 independent chains
                ar += __shfl_xor_sync(0xFFFFFFFFu, ar, off);
                az += __shfl_xor_sync(0xFFFFFFFFu, az, off);
                an += __shfl_xor_sync(0xFFFFFFFFu, an, off);
            }
            if (lane == q) { rr = ar; zz = az; nnacc = an; }
        }
        const int nb = (t + 1) & 1;
        if (lane < 4) {
            const int b = bbase + lane;
            float r = __fdividef(1.f, 1.f + __expf(-(xr + rr + bhr)));
            float z = __fdividef(1.f, 1.f + __expf(-(xz + zz + bhz)));
            float targ = xn + r * (nnacc + bhn);
            targ = fminf(fmaxf(targ, -15.f), 15.f);
            float e2 = __expf(2.f * targ);
            float nv = __fdividef(e2 - 1.f, e2 + 1.f);     // tanh
            float hnew = (1.f - z) * nv + z * hold;
            g_hbuf[nb][b * HH + j] = hnew;
            g_hs[((size_t)b * TT + t) * HH + j] = __float2bfloat16(hnew);
        }

        // ---- grid barrier (R7 aggregator: monotone flags + release word) ----
        __syncthreads();
        const unsigned tgt = base + (unsigned)t + 1u;
        if (tid == 0) {
            __threadfence();                   // publish this CTA's h stores
            g_arrive[blockIdx.x] = tgt;
        }
        if (blockIdx.x == 0) {
            if (tid < NBLK) { while (g_arrive[tid] < tgt) { } }
            __syncthreads();
            if (tid == 0) { __threadfence(); g_gen2 = tgt; }
        } else {
            if (tid == 0) { while (g_gen2 < tgt) { } __threadfence(); }
        }
        __syncthreads();

        // reload full h (float4)
        {
            const float4* src = (const float4*)g_hbuf[nb];
            float4* dst = (float4*)hsm;
#pragma unroll
            for (int i = 0; i < 4; i++) dst[tid + 512 * i] = __ldcg(&src[tid + 512 * i]);
        }
        __syncthreads();
    }
    // hidden output (fp32) appended after log_probs; final buffer is nb=0
    if (blockIdx.x == 0) {
        for (int i = tid; i < BB * HH; i += 512)
            out[(size_t)MROWS * VV + i] = __ldcg(&g_hbuf[0][i]);
    }
}

// ---------------- K3: logits = gru_out @ w_out^T (bf16 WMMA, f32 acc) ------
// R7-measured config: 128x256 block tile, 8 warps (2x4), 64x64 warp tile,
// LD=40, 2-stage cp.async double buffering (60 KB dynamic smem).
#define LG_LD 40
#define A_ST (128 * LG_LD)   // 5120 elems per A stage
#define B_ST (256 * LG_LD)   // 10240 elems per B stage

__device__ __forceinline__ void cp16(__nv_bfloat16* smem_dst, const __nv_bfloat16* gsrc) {
    unsigned sa = (unsigned)__cvta_generic_to_shared(smem_dst);
    asm volatile("cp.async.cg.shared.global [%0], [%1], 16;" :: "r"(sa), "l"(gsrc));
}

__global__ void __launch_bounds__(256) k_logits(float* __restrict__ out) {
    extern __shared__ __nv_bfloat16 smbuf[];
    const int tid = threadIdx.x, warp = tid >> 5;
    const int wm = warp & 1, wn = warp >> 1;     // 2 x 4
    const int m0 = blockIdx.y * 128;
    const int n0 = blockIdx.x * 256;

    wmma::fragment<wmma::accumulator, 16, 16, 16, float> acc[4][4];
#pragma unroll
    for (int i = 0; i < 4; i++)
#pragma unroll
        for (int jj = 0; jj < 4; jj++) wmma::fill_fragment(acc[i][jj], 0.f);

    auto load_stage = [&](int s, int kb) {
        const int k0 = kb * 32;
        __nv_bfloat16* As = smbuf + s * A_ST;
        __nv_bfloat16* Bs = smbuf + 2 * A_ST + s * B_ST;
#pragma unroll
        for (int idx = tid; idx < 512; idx += 256) {      // A: 128x32
            const int r = idx >> 2, c = (idx & 3) * 8;
            cp16(&As[r * LG_LD + c], &g_hs[(size_t)(m0 + r) * HH + k0 + c]);
        }
#pragma unroll
        for (int idx = tid; idx < 1024; idx += 256) {     // B: 256x32
            const int r = idx >> 2, c = (idx & 3) * 8;
            cp16(&Bs[r * LG_LD + c], &g_wout[(size_t)(n0 + r) * HH + k0 + c]);
        }
    };

    load_stage(0, 0);
    asm volatile("cp.async.commit_group;");

    for (int kb = 0; kb < 16; kb++) {
        if (kb + 1 < 16) {
            load_stage((kb + 1) & 1, kb + 1);
            asm volatile("cp.async.commit_group;");
            asm volatile("cp.async.wait_group 1;");
        } else {
            asm volatile("cp.async.wait_group 0;");
        }
        __syncthreads();
        const __nv_bfloat16* As = smbuf + (kb & 1) * A_ST;
        const __nv_bfloat16* Bs = smbuf + 2 * A_ST + (kb & 1) * B_ST;
#pragma unroll
        for (int kk = 0; kk < 32; kk += 16) {
            wmma::fragment<wmma::matrix_a, 16, 16, 16, __nv_bfloat16,
                           wmma::row_major> af[4];
            wmma::fragment<wmma::matrix_b, 16, 16, 16, __nv_bfloat16,
                           wmma::col_major> bf[4];
#pragma unroll
            for (int i = 0; i < 4; i++)
                wmma::load_matrix_sync(af[i], &As[(wm * 64 + i * 16) * LG_LD + kk], LG_LD);
#pragma unroll
            for (int jj = 0; jj < 4; jj++)
                wmma::load_matrix_sync(bf[jj], &Bs[(wn * 64 + jj * 16) * LG_LD + kk], LG_LD);
#pragma unroll
            for (int i = 0; i < 4; i++)
#pragma unroll
                for (int jj = 0; jj < 4; jj++)
                    wmma::mma_sync(acc[i][jj], af[i], bf[jj], acc[i][jj]);
        }
        __syncthreads();
    }
#pragma unroll
    for (int i = 0; i < 4; i++)
#pragma unroll
        for (int jj = 0; jj < 4; jj++)
            wmma::store_matrix_sync(
                &out[(size_t)(m0 + wm * 64 + i * 16) * VV + n0 + wn * 64 + jj * 16],
                acc[i][jj], VV, wmma::mem_row_major);
}

// ---------------- K4: in-place log_softmax (FMA-pipe exp, bias folded) -----
__global__ void __launch_bounds__(256) k_lsm(const float* __restrict__ b_out,
                                             float* __restrict__ out) {
    __shared__ float sm[256], ss[256];
    const int tid = threadIdx.x;
    const size_t row = blockIdx.x;
    float* lg = out + row * VV;

    float m = -1e30f, s = 0.f;
    for (int i = tid; i < VV; i += 256) {
        float x = lg[i] + __ldg(&b_out[i]);
        if (x > m) { s = fmaf(s, fexp_neg(m - x), 1.f); m = x; }
        else s += fexp_neg(x - m);
    }
    sm[tid] = m; ss[tid] = s;
    __syncthreads();
    for (int off = 128; off; off >>= 1) {
        if (tid < off) {
            float m2 = sm[tid + off], s2 = ss[tid + off];
            float M = fmaxf(sm[tid], m2);
            ss[tid] = ss[tid] * fexp_neg(sm[tid] - M) + s2 * fexp_neg(m2 - M);
            sm[tid] = M;
        }
        __syncthreads();
    }
    const float lse = sm[0] + logf(ss[0]);
    for (int i = tid; i < VV; i += 256) lg[i] = lg[i] + __ldg(&b_out[i]) - lse;
}

// ---------------- launch ---------------------------------------------------
extern "C" void kernel_launch(void* const* d_in, const int* in_sizes, int n_in,
                              void* d_out, int out_size) {
    const float* enc_hidden = (const float*)d_in[1];
    const int*   tgt        = (const int*)d_in[2];
    const float* emb        = (const float*)d_in[3];
    const float* w_ih       = (const float*)d_in[4];
    const float* b_ih       = (const float*)d_in[5];
    const float* w_hh       = (const float*)d_in[6];
    const float* b_hh       = (const float*)d_in[7];
    const float* w_out      = (const float*)d_in[8];
    const float* b_out      = (const float*)d_in[9];
    float* out = (float*)d_out;

    const int lg_smem = 2 * (A_ST + B_ST) * (int)sizeof(__nv_bfloat16);
    cudaFuncSetAttribute(k_logits, cudaFuncAttributeMaxDynamicSharedMemorySize,
                         lg_smem);

    k_convert<<<1024, 256>>>(w_out);

    dim3 gx(GG / 128, MROWS / 128);     // (12, 16)
    k_xproj<<<gx, 256>>>(emb, tgt, w_ih, b_ih);

    k_gru<<<NBLK, 512>>>(enc_hidden, w_hh, b_hh, out);

    dim3 gl(VV / 256, MROWS / 128);     // (125, 16)
    k_logits<<<gl, 256, lg_smem>>>(out);

    k_lsm<<<MROWS, 256>>>(b_out, out);
}